// round 6
// baseline (speedup 1.0000x reference)
#include <cuda_runtime.h>

#define NN 100000
#define EE 3200000
#define F_IN 100
#define HID 16
#define NC 18

// Scratch (static device arrays — zero-initialized at module load)
__device__ __align__(128) float g_hs[NN * HID];    // dinv*[h@W] per node (conv input msg)
__device__ __align__(128) float g_hs2[NN * HID];   // double buffer for conv2
__device__ __align__(128) float g_dinv[NN];
__device__ __align__(128) int   g_deg[NN];         // INVARIANT: zero at call entry
__device__ __align__(128) int   g_rowstart[NN + 1];
__device__ __align__(128) int   g_cursor[NN];
__device__ __align__(128) int   g_col[EE];         // CSR (by dst) column = src
__device__ __align__(128) int   g_btot[128];
__device__ __align__(128) int   g_boff[128];

#define SCAN_B 1024
#define SCAN_G 98   // 98*1024 = 100352 >= NN

// ---------------------------------------------------------------------------
// K1: in-degree count (int4-vectorized index loads). g_deg is zero on entry.
__global__ void k_deg(const int* __restrict__ dst, int E) {
    int t = blockIdx.x * blockDim.x + threadIdx.x;
    int e = t * 4;
    if (e + 3 < E) {
        int4 d = *(const int4*)(dst + e);
        atomicAdd(&g_deg[d.x], 1);
        atomicAdd(&g_deg[d.y], 1);
        atomicAdd(&g_deg[d.z], 1);
        atomicAdd(&g_deg[d.w], 1);
    } else {
        for (int k = e; k < E; k++) atomicAdd(&g_deg[dst[k]], 1);
    }
}

// ---------------------------------------------------------------------------
// K2a/b/c: exclusive prefix scan of deg -> rowstart (+ cursor copy)
__global__ void k_scanA() {
    __shared__ int s[SCAN_B];
    int i = blockIdx.x * SCAN_B + threadIdx.x;
    int v = (i < NN) ? g_deg[i] : 0;
    s[threadIdx.x] = v;
    __syncthreads();
    for (int off = 1; off < SCAN_B; off <<= 1) {
        int t = (threadIdx.x >= off) ? s[threadIdx.x - off] : 0;
        __syncthreads();
        s[threadIdx.x] += t;
        __syncthreads();
    }
    if (i < NN) g_rowstart[i] = s[threadIdx.x] - v;     // exclusive within block
    if (threadIdx.x == SCAN_B - 1) g_btot[blockIdx.x] = s[threadIdx.x];
}

__global__ void k_scanB() {   // 1 block, 128 threads
    __shared__ int s[128];
    int v = (threadIdx.x < SCAN_G) ? g_btot[threadIdx.x] : 0;
    s[threadIdx.x] = v;
    __syncthreads();
    for (int off = 1; off < 128; off <<= 1) {
        int t = (threadIdx.x >= off) ? s[threadIdx.x - off] : 0;
        __syncthreads();
        s[threadIdx.x] += t;
        __syncthreads();
    }
    if (threadIdx.x < SCAN_G) g_boff[threadIdx.x] = s[threadIdx.x] - v;
}

__global__ void k_scanC(int E) {
    int i = blockIdx.x * SCAN_B + threadIdx.x;
    if (i < NN) {
        int r = g_rowstart[i] + g_boff[blockIdx.x];
        g_rowstart[i] = r;
        g_cursor[i] = r;
    }
    if (i == 0) g_rowstart[NN] = E;
}

// ---------------------------------------------------------------------------
// K3: CSR fill — col[pos] = src, pos from per-dst cursor
__global__ void k_fill(const int* __restrict__ src, const int* __restrict__ dst, int E) {
    int t = blockIdx.x * blockDim.x + threadIdx.x;
    int e = t * 4;
    if (e + 3 < E) {
        int4 d = *(const int4*)(dst + e);
        int4 s = *(const int4*)(src + e);
        g_col[atomicAdd(&g_cursor[d.x], 1)] = s.x;
        g_col[atomicAdd(&g_cursor[d.y], 1)] = s.y;
        g_col[atomicAdd(&g_cursor[d.z], 1)] = s.z;
        g_col[atomicAdd(&g_cursor[d.w], 1)] = s.w;
    } else {
        for (int k = e; k < E; k++)
            g_col[atomicAdd(&g_cursor[dst[k]], 1)] = src[k];
    }
}

// ---------------------------------------------------------------------------
// K4: h0 = relu(x@W1+b1); hs = dinv * (h0@Wc0). 64 nodes/block, 256 threads.
// Also re-zeroes g_deg (restores call-entry invariant) — race-free:
// ALL 4 node-threads read deg BEFORE the jq==0 thread zeroes it (__syncwarp).
__global__ void k_node0(const float* __restrict__ x,
                        const float* __restrict__ W1,
                        const float* __restrict__ b1,
                        const float* __restrict__ Wc0) {
    __shared__ __align__(16) float sx[64 * F_IN];          // 25.6 KB
    __shared__ __align__(16) float sW1[F_IN * HID];        // 6.4 KB
    __shared__ __align__(16) float sWc0[HID * HID];
    __shared__ __align__(16) float sh[64 * HID];
    __shared__ __align__(16) float sb1[HID];

    int tid = threadIdx.x;
    for (int i = tid; i < F_IN * HID; i += 256) sW1[i] = W1[i];
    for (int i = tid; i < HID * HID; i += 256) sWc0[i] = Wc0[i];
    if (tid < HID) sb1[tid] = b1[tid];

    int base = blockIdx.x * 64;
    int nrows = NN - base; if (nrows > 64) nrows = 64;
    for (int i = tid; i < nrows * F_IN; i += 256)
        sx[i] = x[(long long)base * F_IN + i];
    __syncthreads();

    int ln = tid >> 2, jq = tid & 3;
    int node = base + ln;
    bool valid = (node < NN);

    float4 a = {0.f, 0.f, 0.f, 0.f};
    if (valid) {
        a = *(const float4*)&sb1[jq * 4];
        const float* xr = &sx[ln * F_IN];
#pragma unroll 4
        for (int k = 0; k < F_IN; k++) {
            float xv = xr[k];
            float4 w = *(const float4*)&sW1[k * HID + jq * 4];
            a.x += xv * w.x; a.y += xv * w.y; a.z += xv * w.z; a.w += xv * w.w;
        }
        a.x = fmaxf(a.x, 0.f); a.y = fmaxf(a.y, 0.f);
        a.z = fmaxf(a.z, 0.f); a.w = fmaxf(a.w, 0.f);
        *(float4*)&sh[ln * HID + jq * 4] = a;
    }
    __syncthreads();

    // Uniform deg read for all 4 threads of the node, BEFORE anyone zeroes it.
    int d = valid ? g_deg[node] : 0;
    float dinv = rsqrtf((float)(d + 1));
    __syncwarp();
    if (valid && jq == 0) {
        g_dinv[node] = dinv;
        g_deg[node] = 0;                 // restore invariant for next call
    }

    if (valid) {
        float4 t = {0.f, 0.f, 0.f, 0.f};
        const float* hr = &sh[ln * HID];
#pragma unroll
        for (int i = 0; i < HID; i++) {
            float hv = hr[i];
            float4 w = *(const float4*)&sWc0[i * HID + jq * 4];
            t.x += hv * w.x; t.y += hv * w.y; t.z += hv * w.z; t.w += hv * w.w;
        }
        float4 o = {dinv * t.x, dinv * t.y, dinv * t.z, dinv * t.w};
        *(float4*)&g_hs[node * HID + jq * 4] = o;
    }
}

// ---------------------------------------------------------------------------
// Warp-collective CSR gather, 32-edge chunks for deep MLP.
// All 32 lanes load col indices; 4 rounds of 8 edges (quad per edge) issue
// their float4 loads back-to-back. Returns aggregate for feature f = lane.
__device__ __forceinline__ float warp_gather(const float* __restrict__ hs,
                                             int node, int lane) {
    int rs = g_rowstart[node];
    int re = g_rowstart[node + 1];
    int esub = lane >> 2, q = lane & 3;   // edge-slot 0..7, feature-quad 0..3
    float4 acc = {0.f, 0.f, 0.f, 0.f};
    for (int b = rs; b < re; b += 32) {
        int le = b + lane;
        int c = (le < re) ? g_col[le] : 0;
        int s0 = __shfl_sync(0xffffffff, c, esub);
        int s1 = __shfl_sync(0xffffffff, c, 8 + esub);
        int s2 = __shfl_sync(0xffffffff, c, 16 + esub);
        int s3 = __shfl_sync(0xffffffff, c, 24 + esub);
        float4 d0 = {0,0,0,0}, d1 = {0,0,0,0}, d2 = {0,0,0,0}, d3 = {0,0,0,0};
        if (b + esub      < re) d0 = *(const float4*)&hs[s0 * HID + q * 4];
        if (b + 8 + esub  < re) d1 = *(const float4*)&hs[s1 * HID + q * 4];
        if (b + 16 + esub < re) d2 = *(const float4*)&hs[s2 * HID + q * 4];
        if (b + 24 + esub < re) d3 = *(const float4*)&hs[s3 * HID + q * 4];
        acc.x += (d0.x + d1.x) + (d2.x + d3.x);
        acc.y += (d0.y + d1.y) + (d2.y + d3.y);
        acc.z += (d0.z + d1.z) + (d2.z + d3.z);
        acc.w += (d0.w + d1.w) + (d2.w + d3.w);
    }
#pragma unroll
    for (int off = 4; off < 32; off <<= 1) {
        acc.x += __shfl_xor_sync(0xffffffff, acc.x, off);
        acc.y += __shfl_xor_sync(0xffffffff, acc.y, off);
        acc.z += __shfl_xor_sync(0xffffffff, acc.z, off);
        acc.w += __shfl_xor_sync(0xffffffff, acc.w, off);
    }
    // redistribute: lane f wants component (f&3) of quad (f>>2)'s sum
    int q2 = lane >> 2, c2 = lane & 3;
    float ax = __shfl_sync(0xffffffff, acc.x, q2);
    float ay = __shfl_sync(0xffffffff, acc.y, q2);
    float az = __shfl_sync(0xffffffff, acc.z, q2);
    float aw = __shfl_sync(0xffffffff, acc.w, q2);
    return (c2 == 0) ? ax : (c2 == 1) ? ay : (c2 == 2) ? az : aw;
}

// ---------------------------------------------------------------------------
// K5: conv1 aggregate + relu + @Wc1 + dinv, fused. Warp per node. hs -> hs2.
__global__ void k_gather_mid(const float* __restrict__ bc,
                             const float* __restrict__ Wnext) {
    __shared__ float sW[HID * HID + 32];   // padded: lanes>=16 dead-read up to [271]
    __shared__ float sb[HID];
    int tid = threadIdx.x;
    for (int i = tid; i < HID * HID; i += 256) sW[i] = Wnext[i];
    for (int i = tid + HID * HID; i < HID * HID + 32; i += 256) sW[i] = 0.f;
    if (tid < HID) sb[tid] = bc[tid];
    __syncthreads();

    int warp = tid >> 5, lane = tid & 31;
    int node = blockIdx.x * 8 + warp;     // NN % 8 == 0

    float agg = warp_gather(g_hs, node, lane);
    float dinv = g_dinv[node];
    float h = 0.f;
    if (lane < HID)
        h = fmaxf(dinv * (agg + g_hs[node * HID + lane]) + sb[lane], 0.f);

    float t = 0.f;
#pragma unroll
    for (int i = 0; i < HID; i++) {
        float hi = __shfl_sync(0xffffffff, h, i);
        t += hi * sW[i * HID + lane];     // lanes>=16 read padded zeros, discarded
    }
    if (lane < HID) g_hs2[node * HID + lane] = dinv * t;
}

// ---------------------------------------------------------------------------
// K6: conv2 aggregate + relu + @W2 + b2 + log_softmax. Warp per node.
__global__ void k_gather_out(const float* __restrict__ bc1,
                             const float* __restrict__ W2,
                             const float* __restrict__ b2,
                             float* __restrict__ out) {
    __shared__ float sW2[HID * NC];        // 288 floats — strided staging loop!
    __shared__ float sb2[NC];
    __shared__ float sbc[HID];
    int tid = threadIdx.x;
    for (int i = tid; i < HID * NC; i += 256) sW2[i] = W2[i];
    if (tid < NC) sb2[tid] = b2[tid];
    if (tid < HID) sbc[tid] = bc1[tid];
    __syncthreads();

    int warp = tid >> 5, lane = tid & 31;
    int node = blockIdx.x * 8 + warp;

    float agg = warp_gather(g_hs2, node, lane);
    float dinv = g_dinv[node];
    float h = 0.f;
    if (lane < HID)
        h = fmaxf(dinv * (agg + g_hs2[node * HID + lane]) + sbc[lane], 0.f);

    float o = (lane < NC) ? sb2[lane] : -1e30f;
#pragma unroll
    for (int i = 0; i < HID; i++) {
        float hi = __shfl_sync(0xffffffff, h, i);
        if (lane < NC) o += hi * sW2[i * NC + lane];
    }
    float m = o;
#pragma unroll
    for (int off = 16; off; off >>= 1) m = fmaxf(m, __shfl_xor_sync(0xffffffff, m, off));
    float ex = (lane < NC) ? __expf(o - m) : 0.f;
    float s = ex;
#pragma unroll
    for (int off = 16; off; off >>= 1) s += __shfl_xor_sync(0xffffffff, s, off);
    float ls = m + __logf(s);
    if (lane < NC) out[node * NC + lane] = o - ls;
}

// ---------------------------------------------------------------------------
extern "C" void kernel_launch(void* const* d_in, const int* in_sizes, int n_in,
                              void* d_out, int out_size) {
    const float* x   = (const float*)d_in[0];
    const int*   ei  = (const int*)d_in[1];     // int32 indices
    const float* W1  = (const float*)d_in[2];
    const float* b1  = (const float*)d_in[3];
    const float* Wc0 = (const float*)d_in[4];
    const float* bc0 = (const float*)d_in[5];
    const float* Wc1 = (const float*)d_in[6];
    const float* bc1 = (const float*)d_in[7];
    const float* W2  = (const float*)d_in[8];
    const float* b2  = (const float*)d_in[9];
    float* out = (float*)d_out;

    int E = in_sizes[1] / 2;            // 3200000
    const int* src = ei;
    const int* dst = ei + E;

    int eb4 = (E / 4 + 255) / 256;      // edge blocks, 4 edges/thread

    k_deg<<<eb4, 256>>>(dst, E);
    k_scanA<<<SCAN_G, SCAN_B>>>();
    k_scanB<<<1, 128>>>();
    k_scanC<<<SCAN_G, SCAN_B>>>(E);
    k_fill<<<eb4, 256>>>(src, dst, E);
    k_node0<<<(NN + 63) / 64, 256>>>(x, W1, b1, Wc0);
    k_gather_mid<<<NN / 8, 256>>>(bc0, Wc1);
    k_gather_out<<<NN / 8, 256>>>(bc1, W2, b2, out);
}